// round 7
// baseline (speedup 1.0000x reference)
#include <cuda_runtime.h>
#include <cuda_bf16.h>

// Problem constants (match reference_code)
#define Bv     32768
#define LMAXv  24
#define Mv     10
#define Dv     300
#define Vv     36
#define D4     75            // D / 4 (float4 chunks per row)
#define ROW4   (Mv * D4)     // 750 float4 per batch element
#define NB     8             // batch rows per block (32768 % 8 == 0)

__global__ __launch_bounds__(256, 8)
void word_embed_kernel(const float* __restrict__ emb,     // [V, D]
                       const float* __restrict__ pad,     // [1, D]
                       const int*   __restrict__ tokens,  // [B, LMAX]
                       const int*   __restrict__ lengths, // [B]
                       float*       __restrict__ out)     // [B, M, D]
{
    const int b0  = blockIdx.x * NB;
    const int tid = threadIdx.x;

    // Per-(bb,m) descriptors: lo/hi row pointers (pad folded in) + weight.
    __shared__ const float4* s_lo[NB * Mv];
    __shared__ const float4* s_hi[NB * Mv];
    __shared__ float         s_w[NB * Mv];

    const float4* __restrict__ embv = (const float4*)emb;
    const float4* __restrict__ padv = (const float4*)pad;

    if (tid < NB * Mv) {
        const int bb = tid / Mv;          // 0..NB-1
        const int m  = tid - bb * Mv;     // 0..9
        const int b  = b0 + bb;
        const int L  = __ldg(lengths + b);
        const int* tokrow = tokens + b * LMAXv;

        if (L < Mv) {
            if (m < L) {
                const float4* p = embv + __ldg(tokrow + m) * D4;
                s_lo[tid] = p; s_hi[tid] = p; s_w[tid] = 0.0f;
            } else {
                s_lo[tid] = padv; s_hi[tid] = padv; s_w[tid] = 0.0f;
            }
        } else {
            // interpolate branch: src = m * (L-1) / (M-1), align_corners=True
            float pos = (float)m * (float)(L - 1) / (float)(Mv - 1);
            int   lo  = (int)floorf(pos);
            int   hi  = min(lo + 1, L - 1);
            s_lo[tid] = embv + __ldg(tokrow + lo) * D4;
            s_hi[tid] = embv + __ldg(tokrow + hi) * D4;
            s_w[tid]  = pos - (float)lo;
        }
    }
    __syncthreads();

    // ROW4 = 750 = 2*256 + 238: two full strides + one partial (predicated store).
    // The (m,c) decomposition is identical for every bb -> hoist out of the loop.
    const int j0 = tid;
    const int j1 = tid + 256;
    const int j2t = tid + 512;
    const bool p2 = (j2t < ROW4);
    const int j2 = p2 ? j2t : (ROW4 - 1);   // clamp: keeps smem reads in-bounds

    const int m0 = j0 / D4, c0 = j0 - m0 * D4;
    const int m1 = j1 / D4, c1 = j1 - m1 * D4;
    const int m2 = j2 / D4, c2 = j2 - m2 * D4;

    float4* __restrict__ outv = (float4*)out + (size_t)b0 * ROW4;

    #pragma unroll 2
    for (int bb = 0; bb < NB; bb++) {
        const int base = bb * Mv;

        const float4* plo0 = s_lo[base + m0] + c0;
        const float4* phi0 = s_hi[base + m0] + c0;
        const float   w0   = s_w[base + m0];
        const float4* plo1 = s_lo[base + m1] + c1;
        const float4* phi1 = s_hi[base + m1] + c1;
        const float   w1   = s_w[base + m1];
        const float4* plo2 = s_lo[base + m2] + c2;
        const float4* phi2 = s_hi[base + m2] + c2;
        const float   w2   = s_w[base + m2];

        // Front-batch all lo-loads, then predicated hi-loads.
        float4 a0 = __ldg(plo0);
        float4 a1 = __ldg(plo1);
        float4 a2 = __ldg(plo2);
        float4 v0 = (w0 != 0.0f) ? __ldg(phi0) : a0;
        float4 v1 = (w1 != 0.0f) ? __ldg(phi1) : a1;
        float4 v2 = (w2 != 0.0f) ? __ldg(phi2) : a2;

        const float o0 = 1.0f - w0, o1 = 1.0f - w1, o2 = 1.0f - w2;
        float4 r0, r1, r2;
        r0.x = a0.x * o0 + v0.x * w0;  r0.y = a0.y * o0 + v0.y * w0;
        r0.z = a0.z * o0 + v0.z * w0;  r0.w = a0.w * o0 + v0.w * w0;
        r1.x = a1.x * o1 + v1.x * w1;  r1.y = a1.y * o1 + v1.y * w1;
        r1.z = a1.z * o1 + v1.z * w1;  r1.w = a1.w * o1 + v1.w * w1;
        r2.x = a2.x * o2 + v2.x * w2;  r2.y = a2.y * o2 + v2.y * w2;
        r2.z = a2.z * o2 + v2.z * w2;  r2.w = a2.w * o2 + v2.w * w2;

        float4* __restrict__ orow = outv + bb * ROW4;
        orow[j0] = r0;
        orow[j1] = r1;
        if (p2) orow[j2t] = r2;
    }
}

extern "C" void kernel_launch(void* const* d_in, const int* in_sizes, int n_in,
                              void* d_out, int out_size)
{
    const float* emb     = (const float*)d_in[0];   // [36, 300]
    const float* pad     = (const float*)d_in[1];   // [1, 300]
    const int*   tokens  = (const int*)d_in[2];     // [32768, 24]
    const int*   lengths = (const int*)d_in[3];     // [32768]
    float*       out     = (float*)d_out;           // [32768, 10, 300]

    word_embed_kernel<<<Bv / NB, 256>>>(emb, pad, tokens, lengths, out);
}

// round 15
// speedup vs baseline: 1.2926x; 1.2926x over previous
#include <cuda_runtime.h>
#include <cuda_bf16.h>

// Problem constants (match reference_code)
#define Bv     32768
#define LMAXv  24
#define Mv     10
#define Dv     300
#define Vv     36
#define D4     75            // D / 4 (float4 chunks per row)
#define ROW4   (Mv * D4)     // 750 float4 per batch element

__global__ __launch_bounds__(256, 8)
void word_embed_kernel(const float* __restrict__ emb,     // [V, D]
                       const float* __restrict__ pad,     // [1, D]
                       const int*   __restrict__ tokens,  // [B, LMAX]
                       const int*   __restrict__ lengths, // [B]
                       float*       __restrict__ out)     // [B, M, D]
{
    const int b   = blockIdx.x;
    const int tid = threadIdx.x;

    // Per-m descriptors: lo/hi row pointers (pad folded in) + weight.
    __shared__ const float4* s_lo[Mv];
    __shared__ const float4* s_hi[Mv];
    __shared__ float         s_w[Mv];

    const float4* __restrict__ embv = (const float4*)emb;
    const float4* __restrict__ padv = (const float4*)pad;

    // Warp 0: issue the lengths load and the whole token row IN PARALLEL
    // (token-row address depends only on b, not on L -> no serialization).
    // The 24-int row is one 128B line -> a single L1tex wavefront.
    if (tid < 32) {
        const int* tokrow = tokens + b * LMAXv;
        const int  L   = __ldg(lengths + b);                    // all lanes, broadcast
        const int  tok = __ldg(tokrow + min(tid, LMAXv - 1));   // lanes 0..23 distinct

        if (tid < Mv) {
            const int m = tid;
            int   loi, hii;
            float w;
            bool  is_pad;
            if (L < Mv) {
                is_pad = (m >= L);
                loi = is_pad ? 0 : m;
                hii = loi;
                w   = 0.0f;
            } else {
                // interpolate branch: src = m * (L-1) / (M-1), align_corners=True
                is_pad = false;
                float pos = (float)m * (float)(L - 1) / (float)(Mv - 1);
                loi = (int)floorf(pos);
                hii = min(loi + 1, L - 1);
                w   = pos - (float)loi;
            }
            // Gather token values from the lanes that loaded them.
            const int tlo = __shfl_sync(0xffffffffu, tok, loi);
            const int thi = __shfl_sync(0xffffffffu, tok, hii);
            s_lo[m] = is_pad ? padv : (embv + tlo * D4);
            s_hi[m] = is_pad ? padv : (embv + thi * D4);
            s_w[m]  = w;
        } else {
            // keep non-descriptor lanes' shfls well-defined
            __shfl_sync(0xffffffffu, tok, 0);
            __shfl_sync(0xffffffffu, tok, 0);
        }
    }
    __syncthreads();

    // ROW4 = 750 = 2*256 + 238: two full strides + one partial (predicated store).
    const int j0 = tid;
    const int j1 = tid + 256;
    const int j2t = tid + 512;
    const bool p2 = (j2t < ROW4);
    const int j2 = p2 ? j2t : (ROW4 - 1);   // clamp: keeps smem/table reads in-bounds

    const int m0 = j0 / D4, c0 = j0 - m0 * D4;
    const int m1 = j1 / D4, c1 = j1 - m1 * D4;
    const int m2 = j2 / D4, c2 = j2 - m2 * D4;

    const float4* plo0 = s_lo[m0] + c0;  const float4* phi0 = s_hi[m0] + c0;  const float w0 = s_w[m0];
    const float4* plo1 = s_lo[m1] + c1;  const float4* phi1 = s_hi[m1] + c1;  const float w1 = s_w[m1];
    const float4* plo2 = s_lo[m2] + c2;  const float4* phi2 = s_hi[m2] + c2;  const float w2 = s_w[m2];

    // Front-batch all lo-loads, then predicated hi-loads -> MLP ~6.
    float4 a0 = __ldg(plo0);
    float4 a1 = __ldg(plo1);
    float4 a2 = __ldg(plo2);
    float4 b0 = (w0 != 0.0f) ? __ldg(phi0) : a0;
    float4 b1 = (w1 != 0.0f) ? __ldg(phi1) : a1;
    float4 b2 = (w2 != 0.0f) ? __ldg(phi2) : a2;

    const float o0 = 1.0f - w0, o1 = 1.0f - w1, o2 = 1.0f - w2;
    float4 r0, r1, r2;
    r0.x = a0.x * o0 + b0.x * w0;  r0.y = a0.y * o0 + b0.y * w0;
    r0.z = a0.z * o0 + b0.z * w0;  r0.w = a0.w * o0 + b0.w * w0;
    r1.x = a1.x * o1 + b1.x * w1;  r1.y = a1.y * o1 + b1.y * w1;
    r1.z = a1.z * o1 + b1.z * w1;  r1.w = a1.w * o1 + b1.w * w1;
    r2.x = a2.x * o2 + b2.x * w2;  r2.y = a2.y * o2 + b2.y * w2;
    r2.z = a2.z * o2 + b2.z * w2;  r2.w = a2.w * o2 + b2.w * w2;

    float4* __restrict__ outv = (float4*)out + (size_t)b * ROW4;
    outv[j0] = r0;
    outv[j1] = r1;
    if (p2) outv[j2t] = r2;
}

extern "C" void kernel_launch(void* const* d_in, const int* in_sizes, int n_in,
                              void* d_out, int out_size)
{
    const float* emb     = (const float*)d_in[0];   // [36, 300]
    const float* pad     = (const float*)d_in[1];   // [1, 300]
    const int*   tokens  = (const int*)d_in[2];     // [32768, 24]
    const int*   lengths = (const int*)d_in[3];     // [32768]
    float*       out     = (float*)d_out;           // [32768, 10, 300]

    word_embed_kernel<<<Bv, 256>>>(emb, pad, tokens, lengths, out);
}